// round 3
// baseline (speedup 1.0000x reference)
#include <cuda_runtime.h>

#define MAX_NODES  75008
#define MAX_EDGES  1200128
#define F  64
#define F4 (F / 4)
#define SCAN_B 1024
#define MAX_SCAN_BLOCKS 256

// __device__ scratch (allocation-free rule)
__device__ int   g_offset[MAX_NODES];     // CSR start per node
__device__ int   g_cursor[MAX_NODES];     // atomic fill cursor
__device__ int   g_blocksum[MAX_SCAN_BLOCKS];
__device__ int   g_sorted[MAX_EDGES];     // src ids bucketed by dst
__device__ float g_agg[MAX_NODES * F];

// ---------------------------------------------------------------------------
// counts come FREE from degree: count[n] = round(degree[n]) - 1  (deg=indeg+1)
// ---------------------------------------------------------------------------
__device__ __forceinline__ int node_count(const float* degree, int i, int N) {
    return (i < N) ? (__float2int_rn(degree[i]) - 1) : 0;
}

__device__ __forceinline__ int warp_incl_scan(int v) {
    #pragma unroll
    for (int o = 1; o < 32; o <<= 1) {
        int u = __shfl_up_sync(0xffffffffu, v, o);
        if ((threadIdx.x & 31) >= o) v += u;
    }
    return v;
}

// scan pass 1: per-block sums of counts
__global__ void scan1_kernel(const float* __restrict__ degree, int N) {
    int i = blockIdx.x * SCAN_B + threadIdx.x;
    int c = node_count(degree, i, N);
    int w = __reduce_add_sync(0xffffffffu, c);
    __shared__ int ws[32];
    if ((threadIdx.x & 31) == 0) ws[threadIdx.x >> 5] = w;
    __syncthreads();
    if (threadIdx.x < 32) {
        int v = (threadIdx.x < (SCAN_B / 32)) ? ws[threadIdx.x] : 0;
        v = __reduce_add_sync(0xffffffffu, v);
        if (threadIdx.x == 0) g_blocksum[blockIdx.x] = v;
    }
}

// scan pass 2: exclusive scan of block sums (single block, Hillis-Steele)
__global__ void scan2_kernel(int nb) {
    __shared__ int s[MAX_SCAN_BLOCKS];
    int tid = threadIdx.x;
    int v = (tid < nb) ? g_blocksum[tid] : 0;
    s[tid] = v;
    __syncthreads();
    #pragma unroll
    for (int o = 1; o < MAX_SCAN_BLOCKS; o <<= 1) {
        int u = (tid >= o) ? s[tid - o] : 0;
        __syncthreads();
        s[tid] += u;
        __syncthreads();
    }
    if (tid < nb) g_blocksum[tid] = s[tid] - v;   // exclusive
}

// scan pass 3: block-local exclusive scan + base -> offsets & cursors
__global__ void scan3_kernel(const float* __restrict__ degree, int N) {
    int tid = threadIdx.x;
    int i = blockIdx.x * SCAN_B + tid;
    int c = node_count(degree, i, N);

    int lane = tid & 31, wid = tid >> 5;
    int incl = warp_incl_scan(c);
    __shared__ int ws[32];
    if (lane == 31) ws[wid] = incl;
    __syncthreads();
    if (wid == 0) {
        int v = (lane < (SCAN_B / 32)) ? ws[lane] : 0;
        v = warp_incl_scan(v);
        ws[lane] = v;
    }
    __syncthreads();
    int base = (wid ? ws[wid - 1] : 0) + g_blocksum[blockIdx.x];
    int excl = base + incl - c;
    if (i < N) {
        g_offset[i] = excl;
        g_cursor[i] = excl;
    }
}

// bucket edges by dst (atomics only on 4B cursors — tiny traffic)
__global__ void bucket_kernel(const int* __restrict__ src,
                              const int* __restrict__ dst, int E) {
    int e = blockIdx.x * blockDim.x + threadIdx.x;
    if (e < E) {
        int d = __ldg(dst + e);
        int pos = atomicAdd(&g_cursor[d], 1);
        g_sorted[pos] = __ldg(src + e);
    }
}

// gather: half-warp per node, lane owns one float4 chunk; register
// accumulation, single plain store. No atomics on the 256B payload.
__global__ void __launch_bounds__(256)
gather_kernel(const float* __restrict__ feature,
              const float* __restrict__ degree, int N) {
    int t = blockIdx.x * blockDim.x + threadIdx.x;
    int node = t >> 4;
    int c = t & 15;
    if (node >= N) return;

    int start = g_offset[node];
    int cnt = __float2int_rn(__ldg(degree + node)) - 1;

    float4 acc = make_float4(0.f, 0.f, 0.f, 0.f);
    const float4* feat4 = reinterpret_cast<const float4*>(feature);

    #pragma unroll 4
    for (int i = 0; i < cnt; i++) {
        int s = __ldg(g_sorted + start + i);           // converged (broadcast)
        float sc = rsqrtf(__ldg(degree + s));          // converged (broadcast)
        float4 v = __ldg(feat4 + s * F4 + c);
        acc.x = fmaf(sc, v.x, acc.x);
        acc.y = fmaf(sc, v.y, acc.y);
        acc.z = fmaf(sc, v.z, acc.z);
        acc.w = fmaf(sc, v.w, acc.w);
    }
    reinterpret_cast<float4*>(g_agg)[node * F4 + c] = acc;  // covers cnt==0 too
}

// node apply: out[n] = (agg[n] * rsqrt(degree[n])) @ W + b. FFMA-bound.
__global__ void __launch_bounds__(256)
gemm_kernel(const float* __restrict__ degree,
            const float* __restrict__ W,
            const float* __restrict__ b,
            float* __restrict__ out, int N) {
    __shared__ float4 Ws[F * F4];
    __shared__ float4 bs[F4];

    for (int i = threadIdx.x; i < F * F4; i += blockDim.x)
        Ws[i] = reinterpret_cast<const float4*>(W)[i];
    if (threadIdx.x < F4)
        bs[threadIdx.x] = reinterpret_cast<const float4*>(b)[threadIdx.x];
    __syncthreads();

    int row = blockIdx.x * blockDim.x + threadIdx.x;
    if (row >= N) return;

    float acc[F];
    #pragma unroll
    for (int j = 0; j < F4; j++) {
        float4 bb = bs[j];
        acc[4 * j + 0] = bb.x; acc[4 * j + 1] = bb.y;
        acc[4 * j + 2] = bb.z; acc[4 * j + 3] = bb.w;
    }

    float s = rsqrtf(degree[row]);
    const float4* arow = reinterpret_cast<const float4*>(g_agg + (long)row * F);

    #pragma unroll 4
    for (int k4 = 0; k4 < F4; k4++) {
        float4 hv = __ldg(arow + k4);
        hv.x *= s; hv.y *= s; hv.z *= s; hv.w *= s;
        #pragma unroll
        for (int kk = 0; kk < 4; kk++) {
            float h = (kk == 0) ? hv.x : (kk == 1) ? hv.y : (kk == 2) ? hv.z : hv.w;
            int k = k4 * 4 + kk;
            #pragma unroll
            for (int j = 0; j < F4; j++) {
                float4 w = Ws[k * F4 + j];     // warp-uniform smem broadcast
                acc[4 * j + 0] += h * w.x;
                acc[4 * j + 1] += h * w.y;
                acc[4 * j + 2] += h * w.z;
                acc[4 * j + 3] += h * w.w;
            }
        }
    }

    float4* orow = reinterpret_cast<float4*>(out + (long)row * F);
    #pragma unroll
    for (int j = 0; j < F4; j++)
        orow[j] = make_float4(acc[4 * j + 0], acc[4 * j + 1],
                              acc[4 * j + 2], acc[4 * j + 3]);
}

// ---------------------------------------------------------------------------
extern "C" void kernel_launch(void* const* d_in, const int* in_sizes, int n_in,
                              void* d_out, int out_size) {
    const float* feature = (const float*)d_in[0];
    const float* degree  = (const float*)d_in[1];
    const int*   src     = (const int*)d_in[2];
    const int*   dst     = (const int*)d_in[3];
    const float* W       = (const float*)d_in[4];
    const float* b       = (const float*)d_in[5];
    float*       out     = (float*)d_out;

    int N = in_sizes[1];
    int E = in_sizes[2];
    int nb = (N + SCAN_B - 1) / SCAN_B;          // 74 blocks

    scan1_kernel<<<nb, SCAN_B>>>(degree, N);
    scan2_kernel<<<1, MAX_SCAN_BLOCKS>>>(nb);
    scan3_kernel<<<nb, SCAN_B>>>(degree, N);

    bucket_kernel<<<(E + 255) / 256, 256>>>(src, dst, E);

    int gthreads = N * 16;
    gather_kernel<<<(gthreads + 255) / 256, 256>>>(feature, degree, N);

    gemm_kernel<<<(N + 255) / 256, 256>>>(degree, W, b, out, N);
}

// round 4
// speedup vs baseline: 1.0037x; 1.0037x over previous
#include <cuda_runtime.h>

#define MAX_NODES  75008
#define MAX_EDGES  1200128
#define F  64
#define F4 (F / 4)
#define SCAN_B 1024
#define MAX_SCAN_BLOCKS 256

// __device__ scratch (allocation-free rule)
__device__ int   g_offset[MAX_NODES];     // CSR start per node
__device__ int   g_cursor[MAX_NODES];     // atomic fill cursor
__device__ int   g_blocksum[MAX_SCAN_BLOCKS];
__device__ int   g_sorted[MAX_EDGES];     // src ids bucketed by dst
__device__ float g_agg[MAX_NODES * F];

// ---------------------------------------------------------------------------
// counts come FREE from degree: count[n] = round(degree[n]) - 1  (deg=indeg+1)
// ---------------------------------------------------------------------------
__device__ __forceinline__ int node_count(const float* degree, int i, int N) {
    return (i < N) ? (__float2int_rn(degree[i]) - 1) : 0;
}

__device__ __forceinline__ int warp_incl_scan(int v) {
    #pragma unroll
    for (int o = 1; o < 32; o <<= 1) {
        int u = __shfl_up_sync(0xffffffffu, v, o);
        if ((threadIdx.x & 31) >= o) v += u;
    }
    return v;
}

// scan pass 1: per-block sums of counts
__global__ void scan1_kernel(const float* __restrict__ degree, int N) {
    int i = blockIdx.x * SCAN_B + threadIdx.x;
    int c = node_count(degree, i, N);
    int w = __reduce_add_sync(0xffffffffu, c);
    __shared__ int ws[32];
    if ((threadIdx.x & 31) == 0) ws[threadIdx.x >> 5] = w;
    __syncthreads();
    if (threadIdx.x < 32) {
        int v = (threadIdx.x < (SCAN_B / 32)) ? ws[threadIdx.x] : 0;
        v = __reduce_add_sync(0xffffffffu, v);
        if (threadIdx.x == 0) g_blocksum[blockIdx.x] = v;
    }
}

// scan pass 2: exclusive scan of block sums (single block, Hillis-Steele)
__global__ void scan2_kernel(int nb) {
    __shared__ int s[MAX_SCAN_BLOCKS];
    int tid = threadIdx.x;
    int v = (tid < nb) ? g_blocksum[tid] : 0;
    s[tid] = v;
    __syncthreads();
    #pragma unroll
    for (int o = 1; o < MAX_SCAN_BLOCKS; o <<= 1) {
        int u = (tid >= o) ? s[tid - o] : 0;
        __syncthreads();
        s[tid] += u;
        __syncthreads();
    }
    if (tid < nb) g_blocksum[tid] = s[tid] - v;   // exclusive
}

// scan pass 3: block-local exclusive scan + base -> offsets & cursors
__global__ void scan3_kernel(const float* __restrict__ degree, int N) {
    int tid = threadIdx.x;
    int i = blockIdx.x * SCAN_B + tid;
    int c = node_count(degree, i, N);

    int lane = tid & 31, wid = tid >> 5;
    int incl = warp_incl_scan(c);
    __shared__ int ws[32];
    if (lane == 31) ws[wid] = incl;
    __syncthreads();
    if (wid == 0) {
        int v = (lane < (SCAN_B / 32)) ? ws[lane] : 0;
        v = warp_incl_scan(v);
        ws[lane] = v;
    }
    __syncthreads();
    int base = (wid ? ws[wid - 1] : 0) + g_blocksum[blockIdx.x];
    int excl = base + incl - c;
    if (i < N) {
        g_offset[i] = excl;
        g_cursor[i] = excl;
    }
}

// bucket edges by dst (atomics only on 4B cursors — tiny traffic)
__global__ void bucket_kernel(const int* __restrict__ src,
                              const int* __restrict__ dst, int E) {
    int e = blockIdx.x * blockDim.x + threadIdx.x;
    if (e < E) {
        int d = __ldg(dst + e);
        int pos = atomicAdd(&g_cursor[d], 1);
        g_sorted[pos] = __ldg(src + e);
    }
}

// gather: half-warp per node, lane owns one float4 chunk; register
// accumulation, single plain store. No atomics on the 256B payload.
__global__ void __launch_bounds__(256)
gather_kernel(const float* __restrict__ feature,
              const float* __restrict__ degree, int N) {
    int t = blockIdx.x * blockDim.x + threadIdx.x;
    int node = t >> 4;
    int c = t & 15;
    if (node >= N) return;

    int start = g_offset[node];
    int cnt = __float2int_rn(__ldg(degree + node)) - 1;

    float4 acc = make_float4(0.f, 0.f, 0.f, 0.f);
    const float4* feat4 = reinterpret_cast<const float4*>(feature);

    #pragma unroll 4
    for (int i = 0; i < cnt; i++) {
        int s = __ldg(g_sorted + start + i);           // converged (broadcast)
        float sc = rsqrtf(__ldg(degree + s));          // converged (broadcast)
        float4 v = __ldg(feat4 + s * F4 + c);
        acc.x = fmaf(sc, v.x, acc.x);
        acc.y = fmaf(sc, v.y, acc.y);
        acc.z = fmaf(sc, v.z, acc.z);
        acc.w = fmaf(sc, v.w, acc.w);
    }
    reinterpret_cast<float4*>(g_agg)[node * F4 + c] = acc;  // covers cnt==0 too
}

// node apply: out[n] = (agg[n] * rsqrt(degree[n])) @ W + b. FFMA-bound.
__global__ void __launch_bounds__(256)
gemm_kernel(const float* __restrict__ degree,
            const float* __restrict__ W,
            const float* __restrict__ b,
            float* __restrict__ out, int N) {
    __shared__ float4 Ws[F * F4];
    __shared__ float4 bs[F4];

    for (int i = threadIdx.x; i < F * F4; i += blockDim.x)
        Ws[i] = reinterpret_cast<const float4*>(W)[i];
    if (threadIdx.x < F4)
        bs[threadIdx.x] = reinterpret_cast<const float4*>(b)[threadIdx.x];
    __syncthreads();

    int row = blockIdx.x * blockDim.x + threadIdx.x;
    if (row >= N) return;

    float acc[F];
    #pragma unroll
    for (int j = 0; j < F4; j++) {
        float4 bb = bs[j];
        acc[4 * j + 0] = bb.x; acc[4 * j + 1] = bb.y;
        acc[4 * j + 2] = bb.z; acc[4 * j + 3] = bb.w;
    }

    float s = rsqrtf(degree[row]);
    const float4* arow = reinterpret_cast<const float4*>(g_agg + (long)row * F);

    #pragma unroll 4
    for (int k4 = 0; k4 < F4; k4++) {
        float4 hv = __ldg(arow + k4);
        hv.x *= s; hv.y *= s; hv.z *= s; hv.w *= s;
        #pragma unroll
        for (int kk = 0; kk < 4; kk++) {
            float h = (kk == 0) ? hv.x : (kk == 1) ? hv.y : (kk == 2) ? hv.z : hv.w;
            int k = k4 * 4 + kk;
            #pragma unroll
            for (int j = 0; j < F4; j++) {
                float4 w = Ws[k * F4 + j];     // warp-uniform smem broadcast
                acc[4 * j + 0] += h * w.x;
                acc[4 * j + 1] += h * w.y;
                acc[4 * j + 2] += h * w.z;
                acc[4 * j + 3] += h * w.w;
            }
        }
    }

    float4* orow = reinterpret_cast<float4*>(out + (long)row * F);
    #pragma unroll
    for (int j = 0; j < F4; j++)
        orow[j] = make_float4(acc[4 * j + 0], acc[4 * j + 1],
                              acc[4 * j + 2], acc[4 * j + 3]);
}

// ---------------------------------------------------------------------------
extern "C" void kernel_launch(void* const* d_in, const int* in_sizes, int n_in,
                              void* d_out, int out_size) {
    const float* feature = (const float*)d_in[0];
    const float* degree  = (const float*)d_in[1];
    const int*   src     = (const int*)d_in[2];
    const int*   dst     = (const int*)d_in[3];
    const float* W       = (const float*)d_in[4];
    const float* b       = (const float*)d_in[5];
    float*       out     = (float*)d_out;

    int N = in_sizes[1];
    int E = in_sizes[2];
    int nb = (N + SCAN_B - 1) / SCAN_B;          // 74 blocks

    scan1_kernel<<<nb, SCAN_B>>>(degree, N);
    scan2_kernel<<<1, MAX_SCAN_BLOCKS>>>(nb);
    scan3_kernel<<<nb, SCAN_B>>>(degree, N);

    bucket_kernel<<<(E + 255) / 256, 256>>>(src, dst, E);

    int gthreads = N * 16;
    gather_kernel<<<(gthreads + 255) / 256, 256>>>(feature, degree, N);

    gemm_kernel<<<(N + 255) / 256, 256>>>(degree, W, b, out, N);
}